// round 12
// baseline (speedup 1.0000x reference)
#include <cuda_runtime.h>
#include <cuda_fp16.h>
#include <math.h>
#include <stdint.h>

typedef unsigned int u32;
typedef unsigned short u16;

#define CDIM  192
#define HWDIM 256
#define SHIFT 4
#define NWIN  4096

// ---- smem byte offsets ----
// X/AO fp16 plane: u32 words [kpair 96][px stride 72] = 27648 B
// STG/QS: qkv staging + post-conv q,k fp16: [576ch][33 h2-words] = 76032 B (in-place conv)
// VT: v transposed [px 64][u32 stride 99] = 25344 B, aliases v-channel staging (stg+50688)
// NRM: [6 heads][2][32] f32 norms = 1536 B
#define OFF_X    0
#define OFF_STG  27648
#define OFF_VT   (27648 + 50688)
#define OFF_NRM  (27648 + 76032)
#define SMEM_DYN (27648 + 76032 + 1536)     // 105216 B -> 2 CTAs/SM

// fragment-ordered fp16 weights (hi only): [mtile 48][kstep 12][lane 32] uint4
// mtiles 0..35 = qkv (576 rows), 36..47 = proj (192 rows)
__device__ uint4 g_wfrag[48 * 12 * 32];

__device__ __forceinline__ u16 f16b(float f) {
    __half h = __float2half_rn(f);
    return *reinterpret_cast<u16*>(&h);
}
__device__ __forceinline__ u32 packh2(float a, float b) {
    __half2 h = __floats2half2_rn(a, b);
    return *reinterpret_cast<u32*>(&h);
}
__device__ __forceinline__ float2 h2f2(u32 w) {
    __half2 h = *reinterpret_cast<__half2*>(&w);
    return __half22float2(h);
}

__global__ void prep_wfrag(const float* __restrict__ qkv_w,
                           const float* __restrict__ proj_w)
{
    int idx = blockIdx.x * blockDim.x + threadIdx.x;
    if (idx >= 48 * 12 * 32) return;
    const int mtg = idx / (12 * 32);
    const int ks  = (idx / 32) % 12;
    const int lane = idx & 31;
    const int t = lane & 3, g = lane >> 2;

    uint4 hi4;
    u32* hp = (u32*)&hi4;
    #pragma unroll
    for (int c2 = 0; c2 < 2; ++c2) {
        #pragma unroll
        for (int r2 = 0; r2 < 2; ++r2) {
            const int row = mtg * 16 + g + r2 * 8;
            const int col = ks * 16 + 2 * t + c2 * 8;
            float w0, w1;
            if (mtg < 36) {
                w0 = qkv_w[row * 192 + col];
                w1 = qkv_w[row * 192 + col + 1];
            } else {
                const int r = row - 576;
                w0 = proj_w[r * 192 + col];
                w1 = proj_w[r * 192 + col + 1];
            }
            const int ri = c2 * 2 + r2;
            hp[ri] = (u32)f16b(w0) | ((u32)f16b(w1) << 16);
        }
    }
    g_wfrag[(mtg * 12 + ks) * 32 + lane] = hi4;
}

__device__ __forceinline__ void mma_h(float* d, const u32* a, u32 b0, u32 b1)
{
    asm volatile(
        "mma.sync.aligned.m16n8k16.row.col.f32.f16.f16.f32 "
        "{%0,%1,%2,%3}, {%4,%5,%6,%7}, {%8,%9}, {%0,%1,%2,%3};"
        : "+f"(d[0]), "+f"(d[1]), "+f"(d[2]), "+f"(d[3])
        : "r"(a[0]), "r"(a[1]), "r"(a[2]), "r"(a[3]), "r"(b0), "r"(b1));
}

__global__ __launch_bounds__(384, 2)
void win_attn_mma(const float* __restrict__ x,
                  const float* __restrict__ dw_w,
                  const float* __restrict__ temperature,
                  float* __restrict__ out)
{
    extern __shared__ char smb[];
    u32* X    = (u32*)(smb + OFF_X);
    u32* stg  = (u32*)(smb + OFF_STG);
    u32* vt   = (u32*)(smb + OFF_VT);
    float* nrm = (float*)(smb + OFF_NRM);

    const int tid = threadIdx.x, wid = tid >> 5, lane = tid & 31;
    const int t = lane & 3, g = lane >> 2;
    const int win = blockIdx.x;
    const int b = win >> 10, wh = (win >> 5) & 31, ww = win & 31;
    const int h0 = wh * 8 + SHIFT, w0 = ww * 8 + SHIFT;

    // ---- load x window (-SHIFT roll) -> fp16 plane [kpair][px stride 72] ----
    for (int i = tid; i < 1536; i += 384) {           // 96 ch-pairs x 8 rows x 2 quads
        const int c2 = i >> 4, r = (i >> 1) & 7, q = i & 1;
        const int gh = (h0 + r) & 255, gw = (w0 + q * 4) & 255;
        const float* p0 = x + (((size_t)(b * CDIM + 2 * c2)) << 16) + gh * 256 + gw;
        float4 va = *(const float4*)(p0);
        float4 vb = *(const float4*)(p0 + 65536);
        uint4 st;
        st.x = (u32)f16b(va.x) | ((u32)f16b(vb.x) << 16);
        st.y = (u32)f16b(va.y) | ((u32)f16b(vb.y) << 16);
        st.z = (u32)f16b(va.z) | ((u32)f16b(vb.z) << 16);
        st.w = (u32)f16b(va.w) | ((u32)f16b(vb.w) << 16);
        *(uint4*)(X + c2 * 72 + r * 8 + q * 4) = st;
    }
    __syncthreads();

    // ================= qkv GEMM: 3 M-passes of 16 rows per warp =================
    #pragma unroll 1
    for (int p = 0; p < 3; ++p) {
        float acc[8][4];
        #pragma unroll
        for (int nt = 0; nt < 8; ++nt)
            #pragma unroll
            for (int i = 0; i < 4; ++i) acc[nt][i] = 0.f;

        const int mtg = wid * 3 + p;
        #pragma unroll 1
        for (int ks = 0; ks < 12; ++ks) {
            uint4 Ah = g_wfrag[(mtg * 12 + ks) * 32 + lane];
            const int base = (8 * ks + t) * 72 + g;
            #pragma unroll
            for (int nt = 0; nt < 8; ++nt) {
                const u32 b0 = X[base + 8 * nt];
                const u32 b1 = X[base + 8 * nt + 288];
                mma_h(acc[nt], (const u32*)&Ah, b0, b1);
            }
        }
        const int ch0 = wid * 48 + p * 16 + g;
        #pragma unroll
        for (int nt = 0; nt < 8; ++nt) {
            stg[ch0 * 33 + nt * 4 + t]       = packh2(acc[nt][0], acc[nt][1]);
            stg[(ch0 + 8) * 33 + nt * 4 + t] = packh2(acc[nt][2], acc[nt][3]);
        }
    }
    __syncthreads();

    // ================= depthwise 3x3 (+ fused L2 norms for q,k) =================
    // q,k channels (0..383): in-place rolling conv, ch = tid; norms accumulated in-flight
    {
        const int ch = tid;
        float wd[9];
        #pragma unroll
        for (int i = 0; i < 9; ++i) wd[i] = dw_w[ch * 9 + i];
        float rm1[8], rc[8], rp1[8];
        #pragma unroll
        for (int j = 0; j < 8; ++j) rm1[j] = 0.f;
        #pragma unroll
        for (int i = 0; i < 4; ++i) {
            float2 v = h2f2(stg[ch * 33 + i]);
            rc[2 * i] = v.x; rc[2 * i + 1] = v.y;
        }
        float ss = 0.f;
        #pragma unroll
        for (int r = 0; r < 8; ++r) {
            if (r < 7) {
                #pragma unroll
                for (int i = 0; i < 4; ++i) {
                    float2 v = h2f2(stg[ch * 33 + (r + 1) * 4 + i]);
                    rp1[2 * i] = v.x; rp1[2 * i + 1] = v.y;
                }
            } else {
                #pragma unroll
                for (int j = 0; j < 8; ++j) rp1[j] = 0.f;
            }
            float o[8];
            #pragma unroll
            for (int c = 0; c < 8; ++c) {
                float a = rm1[c] * wd[1] + rc[c] * wd[4] + rp1[c] * wd[7];
                if (c > 0) a += rm1[c - 1] * wd[0] + rc[c - 1] * wd[3] + rp1[c - 1] * wd[6];
                if (c < 7) a += rm1[c + 1] * wd[2] + rc[c + 1] * wd[5] + rp1[c + 1] * wd[8];
                o[c] = a;
            }
            #pragma unroll
            for (int c = 0; c < 8; ++c) {
                // norm uses fp16-rounded values (matches prior behavior closely enough;
                // f16 round then square)
                float oh = __half2float(__float2half_rn(o[c]));
                ss += oh * oh;
            }
            #pragma unroll
            for (int i = 0; i < 4; ++i)
                stg[ch * 33 + r * 4 + i] = packh2(o[2 * i], o[2 * i + 1]);
            #pragma unroll
            for (int j = 0; j < 8; ++j) { rm1[j] = rc[j]; rc[j] = rp1[j]; }
        }
        const float rs = 1.f / fmaxf(sqrtf(ss), 1e-12f);
        if (ch < 192) {
            const int hh = ch >> 5;
            nrm[hh * 64 + (ch & 31)] = rs * temperature[hh];      // q side: fold temp
        } else {
            const int kc = ch - 192;
            nrm[(kc >> 5) * 64 + 32 + (kc & 31)] = rs;            // k side
        }
    }
    // v channels (384..575): register-stage, barrier, conv -> transposed vt
    {
        u32 s[32];
        if (tid < 192) {
            const int vch = 384 + tid;
            #pragma unroll
            for (int i = 0; i < 32; ++i) s[i] = stg[vch * 33 + i];
        }
        __syncthreads();
        if (tid < 192) {
            const int vch = 384 + tid;
            float wd[9];
            #pragma unroll
            for (int i = 0; i < 9; ++i) wd[i] = dw_w[vch * 9 + i];
            float rm1[8], rc[8], rp1[8];
            #pragma unroll
            for (int j = 0; j < 8; ++j) rm1[j] = 0.f;
            #pragma unroll
            for (int i = 0; i < 4; ++i) {
                float2 v = h2f2(s[i]);
                rc[2 * i] = v.x; rc[2 * i + 1] = v.y;
            }
            const u32 half_off = (u32)(tid & 1) * 2u;
            const u32 word_off = (u32)(tid >> 1);
            #pragma unroll
            for (int r = 0; r < 8; ++r) {
                if (r < 7) {
                    #pragma unroll
                    for (int i = 0; i < 4; ++i) {
                        float2 v = h2f2(s[(r + 1) * 4 + i]);
                        rp1[2 * i] = v.x; rp1[2 * i + 1] = v.y;
                    }
                } else {
                    #pragma unroll
                    for (int j = 0; j < 8; ++j) rp1[j] = 0.f;
                }
                #pragma unroll
                for (int c = 0; c < 8; ++c) {
                    float a = rm1[c] * wd[1] + rc[c] * wd[4] + rp1[c] * wd[7];
                    if (c > 0) a += rm1[c - 1] * wd[0] + rc[c - 1] * wd[3] + rp1[c - 1] * wd[6];
                    if (c < 7) a += rm1[c + 1] * wd[2] + rc[c + 1] * wd[5] + rp1[c + 1] * wd[8];
                    const int px = r * 8 + c;
                    *(u16*)((char*)vt + ((u32)px * 99u + word_off) * 4u + half_off) = f16b(a);
                }
                #pragma unroll
                for (int j = 0; j < 8; ++j) { rm1[j] = rc[j]; rc[j] = rp1[j]; }
            }
        }
    }
    __syncthreads();

    // ================= attention (tensor-core): 2 warps per head =================
    const int h = wid >> 1, sub = wid & 1;
    u32 pr[8];
    {
        float qk[4][4];
        #pragma unroll
        for (int nt = 0; nt < 4; ++nt)
            #pragma unroll
            for (int i = 0; i < 4; ++i) qk[nt][i] = 0.f;
        const int qrow = h * 32 + sub * 16;
        #pragma unroll
        for (int ks = 0; ks < 4; ++ks) {
            u32 a[4];
            const int aw = (qrow + g) * 33 + ks * 8 + t;
            a[0] = stg[aw];
            a[1] = stg[aw + 8 * 33];
            a[2] = stg[aw + 4];
            a[3] = stg[aw + 8 * 33 + 4];
            #pragma unroll
            for (int nt = 0; nt < 4; ++nt) {
                const int bw = (192 + h * 32 + nt * 8 + g) * 33 + ks * 8 + t;
                mma_h(qk[nt], a, stg[bw], stg[bw + 4]);
            }
        }
        const float rqA = nrm[h * 64 + sub * 16 + g];          // temp pre-folded
        const float rqB = nrm[h * 64 + sub * 16 + g + 8];
        float vA[8], vB[8];
        #pragma unroll
        for (int nt = 0; nt < 4; ++nt) {
            const float rk0 = nrm[h * 64 + 32 + nt * 8 + 2 * t];
            const float rk1 = nrm[h * 64 + 32 + nt * 8 + 2 * t + 1];
            vA[2 * nt]     = qk[nt][0] * rqA * rk0;
            vA[2 * nt + 1] = qk[nt][1] * rqA * rk1;
            vB[2 * nt]     = qk[nt][2] * rqB * rk0;
            vB[2 * nt + 1] = qk[nt][3] * rqB * rk1;
        }
        float mA = vA[0], mB = vB[0];
        #pragma unroll
        for (int i = 1; i < 8; ++i) { mA = fmaxf(mA, vA[i]); mB = fmaxf(mB, vB[i]); }
        #pragma unroll
        for (int o = 1; o <= 2; o <<= 1) {
            mA = fmaxf(mA, __shfl_xor_sync(0xffffffffu, mA, o));
            mB = fmaxf(mB, __shfl_xor_sync(0xffffffffu, mB, o));
        }
        float sA = 0.f, sB = 0.f;
        #pragma unroll
        for (int i = 0; i < 8; ++i) {
            vA[i] = __expf(vA[i] - mA); sA += vA[i];
            vB[i] = __expf(vB[i] - mB); sB += vB[i];
        }
        #pragma unroll
        for (int o = 1; o <= 2; o <<= 1) {
            sA += __shfl_xor_sync(0xffffffffu, sA, o);
            sB += __shfl_xor_sync(0xffffffffu, sB, o);
        }
        const float iA = 1.f / sA, iB = 1.f / sB;
        #pragma unroll
        for (int nt = 0; nt < 4; ++nt) {
            pr[nt]     = packh2(vA[2 * nt] * iA, vA[2 * nt + 1] * iA);
            pr[4 + nt] = packh2(vB[2 * nt] * iB, vB[2 * nt + 1] * iB);
        }
    }
    __syncthreads();

    // store attn probs fp16 into (dead) q-staging region: [head][row 32][stride 17 u32]
    const int attb = h * 1056;
    {
        const int row = sub * 16 + g;
        #pragma unroll
        for (int nt = 0; nt < 4; ++nt) {
            stg[attb + row * 17 + nt * 4 + t]       = pr[nt];
            stg[attb + (row + 8) * 17 + nt * 4 + t] = pr[4 + nt];
        }
    }
    __syncthreads();

    // attn @ v: M=32 out-channels, N=64 px (warp sub covers px sub*32..), K=32
    {
        float av[2][4][4];
        #pragma unroll
        for (int mt = 0; mt < 2; ++mt)
            #pragma unroll
            for (int nt = 0; nt < 4; ++nt)
                #pragma unroll
                for (int i = 0; i < 4; ++i) av[mt][nt][i] = 0.f;

        #pragma unroll
        for (int ks2 = 0; ks2 < 2; ++ks2) {
            u32 bb[4][2];
            #pragma unroll
            for (int nt = 0; nt < 4; ++nt) {
                const int px = sub * 32 + nt * 8 + g;
                const int bw = px * 99 + h * 16 + ks2 * 8 + t;
                bb[nt][0] = vt[bw];
                bb[nt][1] = vt[bw + 4];
            }
            #pragma unroll
            for (int mt = 0; mt < 2; ++mt) {
                u32 a[4];
                const int aw = attb + (mt * 16 + g) * 17 + ks2 * 8 + t;
                a[0] = stg[aw];
                a[1] = stg[aw + 8 * 17];
                a[2] = stg[aw + 4];
                a[3] = stg[aw + 8 * 17 + 4];
                #pragma unroll
                for (int nt = 0; nt < 4; ++nt)
                    mma_h(av[mt][nt], a, bb[nt][0], bb[nt][1]);
            }
        }
        // epilogue -> AO fp16 plane (X region): u16 scatter by channel parity
        #pragma unroll
        for (int mt = 0; mt < 2; ++mt) {
            const int chA = h * 32 + mt * 16 + g;
            const int chB = chA + 8;
            #pragma unroll
            for (int nt = 0; nt < 4; ++nt) {
                const int px0 = sub * 32 + nt * 8 + 2 * t;
                *(u16*)((char*)X + ((chA >> 1) * 72 + px0) * 4 + (chA & 1) * 2)     = f16b(av[mt][nt][0]);
                *(u16*)((char*)X + ((chA >> 1) * 72 + px0 + 1) * 4 + (chA & 1) * 2) = f16b(av[mt][nt][1]);
                *(u16*)((char*)X + ((chB >> 1) * 72 + px0) * 4 + (chB & 1) * 2)     = f16b(av[mt][nt][2]);
                *(u16*)((char*)X + ((chB >> 1) * 72 + px0 + 1) * 4 + (chB & 1) * 2) = f16b(av[mt][nt][3]);
            }
        }
    }
    __syncthreads();

    // ================= proj GEMM: warp owns rows wid*16..+16, direct store =================
    {
        float acc[8][4];
        #pragma unroll
        for (int nt = 0; nt < 8; ++nt)
            #pragma unroll
            for (int i = 0; i < 4; ++i) acc[nt][i] = 0.f;

        const int mtg = 36 + wid;
        #pragma unroll 1
        for (int ks = 0; ks < 12; ++ks) {
            uint4 Ah = g_wfrag[(mtg * 12 + ks) * 32 + lane];
            const int base = (8 * ks + t) * 72 + g;
            #pragma unroll
            for (int nt = 0; nt < 8; ++nt) {
                const u32 b0 = X[base + 8 * nt];
                const u32 b1 = X[base + 8 * nt + 288];
                mma_h(acc[nt], (const u32*)&Ah, b0, b1);
            }
        }
        const int oc0 = wid * 16 + g;
        const int gwp = (w0 + 2 * t) & 255;
        #pragma unroll
        for (int nt = 0; nt < 8; ++nt) {
            const int gh = (h0 + nt) & 255;
            float* p0 = out + (((size_t)(b * CDIM + oc0)) << 16) + gh * 256 + gwp;
            *(float2*)p0 = make_float2(acc[nt][0], acc[nt][1]);
            float* p1 = p0 + (size_t)8 * 65536;
            *(float2*)p1 = make_float2(acc[nt][2], acc[nt][3]);
        }
    }
}

extern "C" void kernel_launch(void* const* d_in, const int* in_sizes, int n_in,
                              void* d_out, int out_size)
{
    const float* x           = (const float*)d_in[0];
    const float* qkv_w       = (const float*)d_in[1];
    const float* dw_w        = (const float*)d_in[2];
    const float* proj_w      = (const float*)d_in[3];
    const float* temperature = (const float*)d_in[4];
    float* out               = (float*)d_out;

    prep_wfrag<<<(48 * 12 * 32 + 255) / 256, 256>>>(qkv_w, proj_w);

    cudaFuncSetAttribute(win_attn_mma, cudaFuncAttributeMaxDynamicSharedMemorySize, SMEM_DYN);
    win_attn_mma<<<NWIN, 384, SMEM_DYN>>>(x, dw_w, temperature, out);
}

// round 13
// speedup vs baseline: 1.4706x; 1.4706x over previous
#include <cuda_runtime.h>
#include <cuda_fp16.h>
#include <math.h>
#include <stdint.h>

typedef unsigned int u32;
typedef unsigned short u16;

#define CDIM  192
#define HWDIM 256
#define SHIFT 4
#define NWIN  4096

// ---- smem byte offsets ----
// X/AO fp16 plane: u32 words [kpair 96][px stride 72] = 27648 B
// STG/QS: qkv staging + post-conv q,k fp16: [576ch][33 h2-words] = 76032 B (in-place conv)
// VT: v transposed [px 64][u32 stride 99] = 25344 B, aliases v-channel staging (stg+50688)
// NRM: [6 heads][2][32] f32 norms = 1536 B
#define OFF_X    0
#define OFF_STG  27648
#define OFF_VT   (27648 + 50688)
#define OFF_NRM  (27648 + 76032)
#define SMEM_DYN (27648 + 76032 + 1536)     // 105216 B -> 2 CTAs/SM

// fragment-ordered fp16 weights (hi only): [mtile 48][kstep 12][lane 32] uint4
// mtiles 0..35 = qkv (576 rows), 36..47 = proj (192 rows)
__device__ uint4 g_wfrag[48 * 12 * 32];

__device__ __forceinline__ u16 f16b(float f) {
    __half h = __float2half_rn(f);
    return *reinterpret_cast<u16*>(&h);
}
__device__ __forceinline__ u32 packh2(float a, float b) {
    __half2 h = __floats2half2_rn(a, b);
    return *reinterpret_cast<u32*>(&h);
}
__device__ __forceinline__ float2 h2f2(u32 w) {
    __half2 h = *reinterpret_cast<__half2*>(&w);
    return __half22float2(h);
}

__global__ void prep_wfrag(const float* __restrict__ qkv_w,
                           const float* __restrict__ proj_w)
{
    int idx = blockIdx.x * blockDim.x + threadIdx.x;
    if (idx >= 48 * 12 * 32) return;
    const int mtg = idx / (12 * 32);
    const int ks  = (idx / 32) % 12;
    const int lane = idx & 31;
    const int t = lane & 3, g = lane >> 2;

    uint4 hi4;
    u32* hp = (u32*)&hi4;
    #pragma unroll
    for (int c2 = 0; c2 < 2; ++c2) {
        #pragma unroll
        for (int r2 = 0; r2 < 2; ++r2) {
            const int row = mtg * 16 + g + r2 * 8;
            const int col = ks * 16 + 2 * t + c2 * 8;
            float w0, w1;
            if (mtg < 36) {
                w0 = qkv_w[row * 192 + col];
                w1 = qkv_w[row * 192 + col + 1];
            } else {
                const int r = row - 576;
                w0 = proj_w[r * 192 + col];
                w1 = proj_w[r * 192 + col + 1];
            }
            const int ri = c2 * 2 + r2;
            hp[ri] = (u32)f16b(w0) | ((u32)f16b(w1) << 16);
        }
    }
    g_wfrag[(mtg * 12 + ks) * 32 + lane] = hi4;
}

__device__ __forceinline__ void mma_h(float* d, const u32* a, u32 b0, u32 b1)
{
    asm volatile(
        "mma.sync.aligned.m16n8k16.row.col.f32.f16.f16.f32 "
        "{%0,%1,%2,%3}, {%4,%5,%6,%7}, {%8,%9}, {%0,%1,%2,%3};"
        : "+f"(d[0]), "+f"(d[1]), "+f"(d[2]), "+f"(d[3])
        : "r"(a[0]), "r"(a[1]), "r"(a[2]), "r"(a[3]), "r"(b0), "r"(b1));
}

__global__ __launch_bounds__(384, 2)
void win_attn_mma(const float* __restrict__ x,
                  const float* __restrict__ dw_w,
                  const float* __restrict__ temperature,
                  float* __restrict__ out)
{
    extern __shared__ char smb[];
    u32* X    = (u32*)(smb + OFF_X);
    u32* stg  = (u32*)(smb + OFF_STG);
    u32* vt   = (u32*)(smb + OFF_VT);
    float* nrm = (float*)(smb + OFF_NRM);

    const int tid = threadIdx.x, wid = tid >> 5, lane = tid & 31;
    const int t = lane & 3, g = lane >> 2;
    const int win = blockIdx.x;
    const int b = win >> 10, wh = (win >> 5) & 31, ww = win & 31;
    const int h0 = wh * 8 + SHIFT, w0 = ww * 8 + SHIFT;

    // ---- load x window (-SHIFT roll) -> fp16 plane [kpair][px stride 72] ----
    for (int i = tid; i < 1536; i += 384) {           // 96 ch-pairs x 8 rows x 2 quads
        const int c2 = i >> 4, r = (i >> 1) & 7, q = i & 1;
        const int gh = (h0 + r) & 255, gw = (w0 + q * 4) & 255;
        const float* p0 = x + (((size_t)(b * CDIM + 2 * c2)) << 16) + gh * 256 + gw;
        float4 va = *(const float4*)(p0);
        float4 vb = *(const float4*)(p0 + 65536);
        const float av[4] = {va.x, va.y, va.z, va.w};
        const float bv[4] = {vb.x, vb.y, vb.z, vb.w};
        #pragma unroll
        for (int j = 0; j < 4; ++j) {
            const int px = r * 8 + q * 4 + j;
            X[c2 * 72 + px] = (u32)f16b(av[j]) | ((u32)f16b(bv[j]) << 16);
        }
    }
    __syncthreads();

    // ===== qkv GEMM: 3 passes, warp tile = 32 rows x 32 px (halved B+A redundancy) =====
    #pragma unroll 1
    for (int p = 0; p < 3; ++p) {
        const int tile = wid + 12 * p;        // 0..35
        const int m_idx = tile >> 1;          // 0..17 (32-row group)
        const int n_half = tile & 1;          // 0/1 (32-px half)

        float acc[2][4][4];
        #pragma unroll
        for (int mt = 0; mt < 2; ++mt)
            #pragma unroll
            for (int nt = 0; nt < 4; ++nt)
                #pragma unroll
                for (int i = 0; i < 4; ++i) acc[mt][nt][i] = 0.f;

        #pragma unroll 1
        for (int ks = 0; ks < 12; ++ks) {
            uint4 Ah0 = g_wfrag[((m_idx * 2 + 0) * 12 + ks) * 32 + lane];
            uint4 Ah1 = g_wfrag[((m_idx * 2 + 1) * 12 + ks) * 32 + lane];
            const int base = (8 * ks + t) * 72 + g + n_half * 32;
            #pragma unroll
            for (int nt = 0; nt < 4; ++nt) {
                const u32 b0 = X[base + 8 * nt];
                const u32 b1 = X[base + 8 * nt + 288];
                mma_h(acc[0][nt], (const u32*)&Ah0, b0, b1);
                mma_h(acc[1][nt], (const u32*)&Ah1, b0, b1);
            }
        }
        #pragma unroll
        for (int mt = 0; mt < 2; ++mt) {
            const int ch0 = (m_idx * 2 + mt) * 16 + g;
            #pragma unroll
            for (int nt = 0; nt < 4; ++nt) {
                stg[ch0 * 33 + n_half * 16 + nt * 4 + t]       = packh2(acc[mt][nt][0], acc[mt][nt][1]);
                stg[(ch0 + 8) * 33 + n_half * 16 + nt * 4 + t] = packh2(acc[mt][nt][2], acc[mt][nt][3]);
            }
        }
    }
    __syncthreads();

    // ================= depthwise 3x3 =================
    // q,k channels (0..383): in-place rolling conv, ch = tid
    {
        const int ch = tid;
        float wd[9];
        #pragma unroll
        for (int i = 0; i < 9; ++i) wd[i] = dw_w[ch * 9 + i];
        float rm1[8], rc[8], rp1[8];
        #pragma unroll
        for (int j = 0; j < 8; ++j) rm1[j] = 0.f;
        #pragma unroll
        for (int i = 0; i < 4; ++i) {
            float2 v = h2f2(stg[ch * 33 + i]);
            rc[2 * i] = v.x; rc[2 * i + 1] = v.y;
        }
        #pragma unroll
        for (int r = 0; r < 8; ++r) {
            if (r < 7) {
                #pragma unroll
                for (int i = 0; i < 4; ++i) {
                    float2 v = h2f2(stg[ch * 33 + (r + 1) * 4 + i]);
                    rp1[2 * i] = v.x; rp1[2 * i + 1] = v.y;
                }
            } else {
                #pragma unroll
                for (int j = 0; j < 8; ++j) rp1[j] = 0.f;
            }
            float o[8];
            #pragma unroll
            for (int c = 0; c < 8; ++c) {
                float a = rm1[c] * wd[1] + rc[c] * wd[4] + rp1[c] * wd[7];
                if (c > 0) a += rm1[c - 1] * wd[0] + rc[c - 1] * wd[3] + rp1[c - 1] * wd[6];
                if (c < 7) a += rm1[c + 1] * wd[2] + rc[c + 1] * wd[5] + rp1[c + 1] * wd[8];
                o[c] = a;
            }
            #pragma unroll
            for (int i = 0; i < 4; ++i)
                stg[ch * 33 + r * 4 + i] = packh2(o[2 * i], o[2 * i + 1]);
            #pragma unroll
            for (int j = 0; j < 8; ++j) { rm1[j] = rc[j]; rc[j] = rp1[j]; }
        }
    }
    // v channels (384..575): register-stage, barrier, conv -> transposed vt
    {
        u32 s[32];
        if (tid < 192) {
            const int vch = 384 + tid;
            #pragma unroll
            for (int i = 0; i < 32; ++i) s[i] = stg[vch * 33 + i];
        }
        __syncthreads();
        if (tid < 192) {
            const int vch = 384 + tid;
            float wd[9];
            #pragma unroll
            for (int i = 0; i < 9; ++i) wd[i] = dw_w[vch * 9 + i];
            float rm1[8], rc[8], rp1[8];
            #pragma unroll
            for (int j = 0; j < 8; ++j) rm1[j] = 0.f;
            #pragma unroll
            for (int i = 0; i < 4; ++i) {
                float2 v = h2f2(s[i]);
                rc[2 * i] = v.x; rc[2 * i + 1] = v.y;
            }
            const u32 half_off = (u32)(tid & 1) * 2u;
            const u32 word_off = (u32)(tid >> 1);
            #pragma unroll
            for (int r = 0; r < 8; ++r) {
                if (r < 7) {
                    #pragma unroll
                    for (int i = 0; i < 4; ++i) {
                        float2 v = h2f2(s[(r + 1) * 4 + i]);
                        rp1[2 * i] = v.x; rp1[2 * i + 1] = v.y;
                    }
                } else {
                    #pragma unroll
                    for (int j = 0; j < 8; ++j) rp1[j] = 0.f;
                }
                #pragma unroll
                for (int c = 0; c < 8; ++c) {
                    float a = rm1[c] * wd[1] + rc[c] * wd[4] + rp1[c] * wd[7];
                    if (c > 0) a += rm1[c - 1] * wd[0] + rc[c - 1] * wd[3] + rp1[c - 1] * wd[6];
                    if (c < 7) a += rm1[c + 1] * wd[2] + rc[c + 1] * wd[5] + rp1[c + 1] * wd[8];
                    const int px = r * 8 + c;
                    *(u16*)((char*)vt + ((u32)px * 99u + word_off) * 4u + half_off) = f16b(a);
                }
                #pragma unroll
                for (int j = 0; j < 8; ++j) { rm1[j] = rc[j]; rc[j] = rp1[j]; }
            }
        }
    }
    __syncthreads();

    // ================= attention (tensor-core): 2 warps per head =================
    const int h = wid >> 1, sub = wid & 1;
    {
        const int nch = (sub ? 192 : 0) + h * 32 + lane;
        float ss = 0.f;
        #pragma unroll
        for (int i = 0; i < 32; ++i) {
            float2 v = h2f2(stg[nch * 33 + i]);
            ss += v.x * v.x + v.y * v.y;
        }
        nrm[(h * 2 + sub) * 32 + lane] = 1.f / fmaxf(sqrtf(ss), 1e-12f);
    }
    __syncthreads();

    u32 pr[8];
    {
        float qk[4][4];
        #pragma unroll
        for (int nt = 0; nt < 4; ++nt)
            #pragma unroll
            for (int i = 0; i < 4; ++i) qk[nt][i] = 0.f;
        const int qrow = h * 32 + sub * 16;
        #pragma unroll
        for (int ks = 0; ks < 4; ++ks) {
            u32 a[4];
            const int aw = (qrow + g) * 33 + ks * 8 + t;
            a[0] = stg[aw];
            a[1] = stg[aw + 8 * 33];
            a[2] = stg[aw + 4];
            a[3] = stg[aw + 8 * 33 + 4];
            #pragma unroll
            for (int nt = 0; nt < 4; ++nt) {
                const int bw = (192 + h * 32 + nt * 8 + g) * 33 + ks * 8 + t;
                mma_h(qk[nt], a, stg[bw], stg[bw + 4]);
            }
        }
        const float temp = temperature[h];
        const float rqA = nrm[h * 64 + sub * 16 + g] * temp;
        const float rqB = nrm[h * 64 + sub * 16 + g + 8] * temp;
        float vA[8], vB[8];
        #pragma unroll
        for (int nt = 0; nt < 4; ++nt) {
            const float rk0 = nrm[h * 64 + 32 + nt * 8 + 2 * t];
            const float rk1 = nrm[h * 64 + 32 + nt * 8 + 2 * t + 1];
            vA[2 * nt]     = qk[nt][0] * rqA * rk0;
            vA[2 * nt + 1] = qk[nt][1] * rqA * rk1;
            vB[2 * nt]     = qk[nt][2] * rqB * rk0;
            vB[2 * nt + 1] = qk[nt][3] * rqB * rk1;
        }
        float mA = vA[0], mB = vB[0];
        #pragma unroll
        for (int i = 1; i < 8; ++i) { mA = fmaxf(mA, vA[i]); mB = fmaxf(mB, vB[i]); }
        #pragma unroll
        for (int o = 1; o <= 2; o <<= 1) {
            mA = fmaxf(mA, __shfl_xor_sync(0xffffffffu, mA, o));
            mB = fmaxf(mB, __shfl_xor_sync(0xffffffffu, mB, o));
        }
        float sA = 0.f, sB = 0.f;
        #pragma unroll
        for (int i = 0; i < 8; ++i) {
            vA[i] = __expf(vA[i] - mA); sA += vA[i];
            vB[i] = __expf(vB[i] - mB); sB += vB[i];
        }
        #pragma unroll
        for (int o = 1; o <= 2; o <<= 1) {
            sA += __shfl_xor_sync(0xffffffffu, sA, o);
            sB += __shfl_xor_sync(0xffffffffu, sB, o);
        }
        const float iA = 1.f / sA, iB = 1.f / sB;
        #pragma unroll
        for (int nt = 0; nt < 4; ++nt) {
            pr[nt]     = packh2(vA[2 * nt] * iA, vA[2 * nt + 1] * iA);
            pr[4 + nt] = packh2(vB[2 * nt] * iB, vB[2 * nt + 1] * iB);
        }
    }
    __syncthreads();

    // store attn probs fp16 into (dead) q-staging region: [head][row 32][stride 17 u32]
    const int attb = h * 1056;
    {
        const int row = sub * 16 + g;
        #pragma unroll
        for (int nt = 0; nt < 4; ++nt) {
            stg[attb + row * 17 + nt * 4 + t]       = pr[nt];
            stg[attb + (row + 8) * 17 + nt * 4 + t] = pr[4 + nt];
        }
    }
    __syncthreads();

    // attn @ v: M=32 out-channels, N=64 px (warp sub covers px sub*32..), K=32
    {
        float av[2][4][4];
        #pragma unroll
        for (int mt = 0; mt < 2; ++mt)
            #pragma unroll
            for (int nt = 0; nt < 4; ++nt)
                #pragma unroll
                for (int i = 0; i < 4; ++i) av[mt][nt][i] = 0.f;

        #pragma unroll
        for (int ks2 = 0; ks2 < 2; ++ks2) {
            u32 bb[4][2];
            #pragma unroll
            for (int nt = 0; nt < 4; ++nt) {
                const int px = sub * 32 + nt * 8 + g;
                const int bw = px * 99 + h * 16 + ks2 * 8 + t;
                bb[nt][0] = vt[bw];
                bb[nt][1] = vt[bw + 4];
            }
            #pragma unroll
            for (int mt = 0; mt < 2; ++mt) {
                u32 a[4];
                const int aw = attb + (mt * 16 + g) * 17 + ks2 * 8 + t;
                a[0] = stg[aw];
                a[1] = stg[aw + 8 * 17];
                a[2] = stg[aw + 4];
                a[3] = stg[aw + 8 * 17 + 4];
                #pragma unroll
                for (int nt = 0; nt < 4; ++nt)
                    mma_h(av[mt][nt], a, bb[nt][0], bb[nt][1]);
            }
        }
        // epilogue -> AO fp16 plane (X region): u16 scatter by channel parity
        #pragma unroll
        for (int mt = 0; mt < 2; ++mt) {
            const int chA = h * 32 + mt * 16 + g;
            const int chB = chA + 8;
            #pragma unroll
            for (int nt = 0; nt < 4; ++nt) {
                const int px0 = sub * 32 + nt * 8 + 2 * t;
                *(u16*)((char*)X + ((chA >> 1) * 72 + px0) * 4 + (chA & 1) * 2)     = f16b(av[mt][nt][0]);
                *(u16*)((char*)X + ((chA >> 1) * 72 + px0 + 1) * 4 + (chA & 1) * 2) = f16b(av[mt][nt][1]);
                *(u16*)((char*)X + ((chB >> 1) * 72 + px0) * 4 + (chB & 1) * 2)     = f16b(av[mt][nt][2]);
                *(u16*)((char*)X + ((chB >> 1) * 72 + px0 + 1) * 4 + (chB & 1) * 2) = f16b(av[mt][nt][3]);
            }
        }
    }
    __syncthreads();

    // ================= proj GEMM: warp owns rows wid*16..+16, direct store =================
    {
        float acc[8][4];
        #pragma unroll
        for (int nt = 0; nt < 8; ++nt)
            #pragma unroll
            for (int i = 0; i < 4; ++i) acc[nt][i] = 0.f;

        const int mtg = 36 + wid;
        #pragma unroll 1
        for (int ks = 0; ks < 12; ++ks) {
            uint4 Ah = g_wfrag[(mtg * 12 + ks) * 32 + lane];
            const int base = (8 * ks + t) * 72 + g;
            #pragma unroll
            for (int nt = 0; nt < 8; ++nt) {
                const u32 b0 = X[base + 8 * nt];
                const u32 b1 = X[base + 8 * nt + 288];
                mma_h(acc[nt], (const u32*)&Ah, b0, b1);
            }
        }
        const int oc0 = wid * 16 + g;
        const int gwp = (w0 + 2 * t) & 255;
        #pragma unroll
        for (int nt = 0; nt < 8; ++nt) {
            const int gh = (h0 + nt) & 255;
            float* p0 = out + (((size_t)(b * CDIM + oc0)) << 16) + gh * 256 + gwp;
            *(float2*)p0 = make_float2(acc[nt][0], acc[nt][1]);
            float* p1 = p0 + (size_t)8 * 65536;
            *(float2*)p1 = make_float2(acc[nt][2], acc[nt][3]);
        }
    }
}

extern "C" void kernel_launch(void* const* d_in, const int* in_sizes, int n_in,
                              void* d_out, int out_size)
{
    const float* x           = (const float*)d_in[0];
    const float* qkv_w       = (const float*)d_in[1];
    const float* dw_w        = (const float*)d_in[2];
    const float* proj_w      = (const float*)d_in[3];
    const float* temperature = (const float*)d_in[4];
    float* out               = (float*)d_out;

    prep_wfrag<<<(48 * 12 * 32 + 255) / 256, 256>>>(qkv_w, proj_w);

    cudaFuncSetAttribute(win_attn_mma, cudaFuncAttributeMaxDynamicSharedMemorySize, SMEM_DYN);
    win_attn_mma<<<NWIN, 384, SMEM_DYN>>>(x, dw_w, temperature, out);
}

// round 15
// speedup vs baseline: 1.5006x; 1.0204x over previous
#include <cuda_runtime.h>
#include <cuda_fp16.h>
#include <math.h>
#include <stdint.h>

typedef unsigned int u32;
typedef unsigned short u16;

#define CDIM  192
#define HWDIM 256
#define SHIFT 4
#define NWIN  4096

// ---- smem byte offsets ----
// X/AO fp16 plane: u32 words [kpair 96][px stride 72] = 27648 B
// STG/QS: qkv staging + post-conv q,k fp16: [576ch][33 h2-words] = 76032 B (in-place conv)
// VT: v transposed [px 64][u32 stride 99] = 25344 B, aliases v-channel staging (stg+50688)
// NRM: [6 heads][2][32] f32 norms = 1536 B
#define OFF_X    0
#define OFF_STG  27648
#define OFF_VT   (27648 + 50688)
#define OFF_NRM  (27648 + 76032)
#define SMEM_DYN (27648 + 76032 + 1536)     // 105216 B -> 2 CTAs/SM

// fragment-ordered fp16 weights (hi only): [mtile 48][kstep 12][lane 32] uint4
// mtiles 0..35 = qkv (576 rows), 36..47 = proj (192 rows)
__device__ uint4 g_wfrag[48 * 12 * 32];

__device__ __forceinline__ u16 f16b(float f) {
    __half h = __float2half_rn(f);
    return *reinterpret_cast<u16*>(&h);
}
__device__ __forceinline__ u32 packh2(float a, float b) {
    __half2 h = __floats2half2_rn(a, b);
    return *reinterpret_cast<u32*>(&h);
}
__device__ __forceinline__ float2 h2f2(u32 w) {
    __half2 h = *reinterpret_cast<__half2*>(&w);
    return __half22float2(h);
}

__global__ void prep_wfrag(const float* __restrict__ qkv_w,
                           const float* __restrict__ proj_w)
{
    int idx = blockIdx.x * blockDim.x + threadIdx.x;
    if (idx >= 48 * 12 * 32) return;
    const int mtg = idx / (12 * 32);
    const int ks  = (idx / 32) % 12;
    const int lane = idx & 31;
    const int t = lane & 3, g = lane >> 2;

    uint4 hi4;
    u32* hp = (u32*)&hi4;
    #pragma unroll
    for (int c2 = 0; c2 < 2; ++c2) {
        #pragma unroll
        for (int r2 = 0; r2 < 2; ++r2) {
            const int row = mtg * 16 + g + r2 * 8;
            const int col = ks * 16 + 2 * t + c2 * 8;
            float w0, w1;
            if (mtg < 36) {
                w0 = qkv_w[row * 192 + col];
                w1 = qkv_w[row * 192 + col + 1];
            } else {
                const int r = row - 576;
                w0 = proj_w[r * 192 + col];
                w1 = proj_w[r * 192 + col + 1];
            }
            const int ri = c2 * 2 + r2;
            hp[ri] = (u32)f16b(w0) | ((u32)f16b(w1) << 16);
        }
    }
    g_wfrag[(mtg * 12 + ks) * 32 + lane] = hi4;
}

__device__ __forceinline__ void mma_h(float* d, const u32* a, u32 b0, u32 b1)
{
    asm volatile(
        "mma.sync.aligned.m16n8k16.row.col.f32.f16.f16.f32 "
        "{%0,%1,%2,%3}, {%4,%5,%6,%7}, {%8,%9}, {%0,%1,%2,%3};"
        : "+f"(d[0]), "+f"(d[1]), "+f"(d[2]), "+f"(d[3])
        : "r"(a[0]), "r"(a[1]), "r"(a[2]), "r"(a[3]), "r"(b0), "r"(b1));
}

__global__ __launch_bounds__(384, 2)
void win_attn_mma(const float* __restrict__ x,
                  const float* __restrict__ dw_w,
                  const float* __restrict__ temperature,
                  float* __restrict__ out)
{
    extern __shared__ char smb[];
    u32* X    = (u32*)(smb + OFF_X);
    u32* stg  = (u32*)(smb + OFF_STG);
    u32* vt   = (u32*)(smb + OFF_VT);
    float* nrm = (float*)(smb + OFF_NRM);

    const int tid = threadIdx.x, wid = tid >> 5, lane = tid & 31;
    const int t = lane & 3, g = lane >> 2;
    const int win = blockIdx.x;
    const int b = win >> 10, wh = (win >> 5) & 31, ww = win & 31;
    const int h0 = wh * 8 + SHIFT, w0 = ww * 8 + SHIFT;

    // ---- load x window (-SHIFT roll) -> fp16 plane [kpair][px stride 72] ----
    for (int i = tid; i < 1536; i += 384) {           // 96 ch-pairs x 8 rows x 2 quads
        const int c2 = i >> 4, r = (i >> 1) & 7, q = i & 1;
        const int gh = (h0 + r) & 255, gw = (w0 + q * 4) & 255;
        const float* p0 = x + (((size_t)(b * CDIM + 2 * c2)) << 16) + gh * 256 + gw;
        float4 va = *(const float4*)(p0);
        float4 vb = *(const float4*)(p0 + 65536);
        const float av[4] = {va.x, va.y, va.z, va.w};
        const float bv[4] = {vb.x, vb.y, vb.z, vb.w};
        #pragma unroll
        for (int j = 0; j < 4; ++j) {
            const int px = r * 8 + q * 4 + j;
            X[c2 * 72 + px] = (u32)f16b(av[j]) | ((u32)f16b(bv[j]) << 16);
        }
    }
    __syncthreads();

    // ===== qkv GEMM: 3 passes, warp tile = 32 rows x 32 px =====
    #pragma unroll 1
    for (int p = 0; p < 3; ++p) {
        const int tile = wid + 12 * p;        // 0..35
        const int m_idx = tile >> 1;          // 0..17 (32-row group)
        const int n_half = tile & 1;          // 0/1 (32-px half)

        float acc[2][4][4];
        #pragma unroll
        for (int mt = 0; mt < 2; ++mt)
            #pragma unroll
            for (int nt = 0; nt < 4; ++nt)
                #pragma unroll
                for (int i = 0; i < 4; ++i) acc[mt][nt][i] = 0.f;

        #pragma unroll 1
        for (int ks = 0; ks < 12; ++ks) {
            uint4 Ah0 = g_wfrag[((m_idx * 2 + 0) * 12 + ks) * 32 + lane];
            uint4 Ah1 = g_wfrag[((m_idx * 2 + 1) * 12 + ks) * 32 + lane];
            const int base = (8 * ks + t) * 72 + g + n_half * 32;
            #pragma unroll
            for (int nt = 0; nt < 4; ++nt) {
                const u32 b0 = X[base + 8 * nt];
                const u32 b1 = X[base + 8 * nt + 288];
                mma_h(acc[0][nt], (const u32*)&Ah0, b0, b1);
                mma_h(acc[1][nt], (const u32*)&Ah1, b0, b1);
            }
        }
        #pragma unroll
        for (int mt = 0; mt < 2; ++mt) {
            const int ch0 = (m_idx * 2 + mt) * 16 + g;
            #pragma unroll
            for (int nt = 0; nt < 4; ++nt) {
                stg[ch0 * 33 + n_half * 16 + nt * 4 + t]       = packh2(acc[mt][nt][0], acc[mt][nt][1]);
                stg[(ch0 + 8) * 33 + n_half * 16 + nt * 4 + t] = packh2(acc[mt][nt][2], acc[mt][nt][3]);
            }
        }
    }
    __syncthreads();

    // ================= depthwise 3x3 =================
    // q,k channels (0..383): in-place rolling conv, ch = tid
    {
        const int ch = tid;
        float wd[9];
        #pragma unroll
        for (int i = 0; i < 9; ++i) wd[i] = dw_w[ch * 9 + i];
        float rm1[8], rc[8], rp1[8];
        #pragma unroll
        for (int j = 0; j < 8; ++j) rm1[j] = 0.f;
        #pragma unroll
        for (int i = 0; i < 4; ++i) {
            float2 v = h2f2(stg[ch * 33 + i]);
            rc[2 * i] = v.x; rc[2 * i + 1] = v.y;
        }
        #pragma unroll
        for (int r = 0; r < 8; ++r) {
            if (r < 7) {
                #pragma unroll
                for (int i = 0; i < 4; ++i) {
                    float2 v = h2f2(stg[ch * 33 + (r + 1) * 4 + i]);
                    rp1[2 * i] = v.x; rp1[2 * i + 1] = v.y;
                }
            } else {
                #pragma unroll
                for (int j = 0; j < 8; ++j) rp1[j] = 0.f;
            }
            float o[8];
            #pragma unroll
            for (int c = 0; c < 8; ++c) {
                float a = rm1[c] * wd[1] + rc[c] * wd[4] + rp1[c] * wd[7];
                if (c > 0) a += rm1[c - 1] * wd[0] + rc[c - 1] * wd[3] + rp1[c - 1] * wd[6];
                if (c < 7) a += rm1[c + 1] * wd[2] + rc[c + 1] * wd[5] + rp1[c + 1] * wd[8];
                o[c] = a;
            }
            #pragma unroll
            for (int i = 0; i < 4; ++i)
                stg[ch * 33 + r * 4 + i] = packh2(o[2 * i], o[2 * i + 1]);
            #pragma unroll
            for (int j = 0; j < 8; ++j) { rm1[j] = rc[j]; rc[j] = rp1[j]; }
        }
    }
    // v channels (384..575): threads<192 register-stage v; after barrier,
    // threads<192 conv v -> transposed vt while threads>=192 compute q,k norms.
    {
        u32 s[32];
        if (tid < 192) {
            const int vch = 384 + tid;
            #pragma unroll
            for (int i = 0; i < 32; ++i) s[i] = stg[vch * 33 + i];
        }
        __syncthreads();   // qk conv complete + v staged (vt aliases v staging)
        if (tid < 192) {
            const int vch = 384 + tid;
            float wd[9];
            #pragma unroll
            for (int i = 0; i < 9; ++i) wd[i] = dw_w[vch * 9 + i];
            float rm1[8], rc[8], rp1[8];
            #pragma unroll
            for (int j = 0; j < 8; ++j) rm1[j] = 0.f;
            #pragma unroll
            for (int i = 0; i < 4; ++i) {
                float2 v = h2f2(s[i]);
                rc[2 * i] = v.x; rc[2 * i + 1] = v.y;
            }
            const u32 half_off = (u32)(tid & 1) * 2u;
            const u32 word_off = (u32)(tid >> 1);
            #pragma unroll
            for (int r = 0; r < 8; ++r) {
                if (r < 7) {
                    #pragma unroll
                    for (int i = 0; i < 4; ++i) {
                        float2 v = h2f2(s[(r + 1) * 4 + i]);
                        rp1[2 * i] = v.x; rp1[2 * i + 1] = v.y;
                    }
                } else {
                    #pragma unroll
                    for (int j = 0; j < 8; ++j) rp1[j] = 0.f;
                }
                #pragma unroll
                for (int c = 0; c < 8; ++c) {
                    float a = rm1[c] * wd[1] + rc[c] * wd[4] + rp1[c] * wd[7];
                    if (c > 0) a += rm1[c - 1] * wd[0] + rc[c - 1] * wd[3] + rp1[c - 1] * wd[6];
                    if (c < 7) a += rm1[c + 1] * wd[2] + rc[c + 1] * wd[5] + rp1[c + 1] * wd[8];
                    const int px = r * 8 + c;
                    *(u16*)((char*)vt + ((u32)px * 99u + word_off) * 4u + half_off) = f16b(a);
                }
                #pragma unroll
                for (int j = 0; j < 8; ++j) { rm1[j] = rc[j]; rc[j] = rp1[j]; }
            }
        } else {
            // norms for q channel jc and k channel 192+jc (reads stg q,k region,
            // disjoint from vt writes)
            const int jc = tid - 192;          // 0..191
            const int hh = jc >> 5, cc = jc & 31;
            float sq = 0.f, sk = 0.f;
            #pragma unroll
            for (int i = 0; i < 32; ++i) {
                float2 vq = h2f2(stg[jc * 33 + i]);
                sq += vq.x * vq.x + vq.y * vq.y;
                float2 vk = h2f2(stg[(192 + jc) * 33 + i]);
                sk += vk.x * vk.x + vk.y * vk.y;
            }
            nrm[hh * 64 + cc]      = (1.f / fmaxf(sqrtf(sq), 1e-12f)) * temperature[hh];
            nrm[hh * 64 + 32 + cc] = 1.f / fmaxf(sqrtf(sk), 1e-12f);
        }
    }
    __syncthreads();

    // ================= attention (tensor-core): 2 warps per head =================
    const int h = wid >> 1, sub = wid & 1;
    u32 pr[8];
    {
        float qk[4][4];
        #pragma unroll
        for (int nt = 0; nt < 4; ++nt)
            #pragma unroll
            for (int i = 0; i < 4; ++i) qk[nt][i] = 0.f;
        const int qrow = h * 32 + sub * 16;
        #pragma unroll
        for (int ks = 0; ks < 4; ++ks) {
            u32 a[4];
            const int aw = (qrow + g) * 33 + ks * 8 + t;
            a[0] = stg[aw];
            a[1] = stg[aw + 8 * 33];
            a[2] = stg[aw + 4];
            a[3] = stg[aw + 8 * 33 + 4];
            #pragma unroll
            for (int nt = 0; nt < 4; ++nt) {
                const int bw = (192 + h * 32 + nt * 8 + g) * 33 + ks * 8 + t;
                mma_h(qk[nt], a, stg[bw], stg[bw + 4]);
            }
        }
        const float rqA = nrm[h * 64 + sub * 16 + g];        // temp pre-folded
        const float rqB = nrm[h * 64 + sub * 16 + g + 8];
        float vA[8], vB[8];
        #pragma unroll
        for (int nt = 0; nt < 4; ++nt) {
            const float rk0 = nrm[h * 64 + 32 + nt * 8 + 2 * t];
            const float rk1 = nrm[h * 64 + 32 + nt * 8 + 2 * t + 1];
            vA[2 * nt]     = qk[nt][0] * rqA * rk0;
            vA[2 * nt + 1] = qk[nt][1] * rqA * rk1;
            vB[2 * nt]     = qk[nt][2] * rqB * rk0;
            vB[2 * nt + 1] = qk[nt][3] * rqB * rk1;
        }
        float mA = vA[0], mB = vB[0];
        #pragma unroll
        for (int i = 1; i < 8; ++i) { mA = fmaxf(mA, vA[i]); mB = fmaxf(mB, vB[i]); }
        #pragma unroll
        for (int o = 1; o <= 2; o <<= 1) {
            mA = fmaxf(mA, __shfl_xor_sync(0xffffffffu, mA, o));
            mB = fmaxf(mB, __shfl_xor_sync(0xffffffffu, mB, o));
        }
        float sA = 0.f, sB = 0.f;
        #pragma unroll
        for (int i = 0; i < 8; ++i) {
            vA[i] = __expf(vA[i] - mA); sA += vA[i];
            vB[i] = __expf(vB[i] - mB); sB += vB[i];
        }
        #pragma unroll
        for (int o = 1; o <= 2; o <<= 1) {
            sA += __shfl_xor_sync(0xffffffffu, sA, o);
            sB += __shfl_xor_sync(0xffffffffu, sB, o);
        }
        const float iA = 1.f / sA, iB = 1.f / sB;
        #pragma unroll
        for (int nt = 0; nt < 4; ++nt) {
            pr[nt]     = packh2(vA[2 * nt] * iA, vA[2 * nt + 1] * iA);
            pr[4 + nt] = packh2(vB[2 * nt] * iB, vB[2 * nt + 1] * iB);
        }
    }
    __syncthreads();

    // store attn probs fp16 into (dead) q-staging region: [head][row 32][stride 17 u32]
    const int attb = h * 1056;
    {
        const int row = sub * 16 + g;
        #pragma unroll
        for (int nt = 0; nt < 4; ++nt) {
            stg[attb + row * 17 + nt * 4 + t]       = pr[nt];
            stg[attb + (row + 8) * 17 + nt * 4 + t] = pr[4 + nt];
        }
    }
    __syncthreads();

    // attn @ v: M=32 out-channels, N=64 px (warp sub covers px sub*32..), K=32
    {
        float av[2][4][4];
        #pragma unroll
        for (int mt = 0; mt < 2; ++mt)
            #pragma unroll
            for (int nt = 0; nt < 4; ++nt)
                #pragma unroll
                for (int i = 0; i < 4; ++i) av[mt][nt][i] = 0.f;

        #pragma unroll
        for (int ks2 = 0; ks2 < 2; ++ks2) {
            u32 bb[4][2];
            #pragma unroll
            for (int nt = 0; nt < 4; ++nt) {
                const int px = sub * 32 + nt * 8 + g;
                const int bw = px * 99 + h * 16 + ks2 * 8 + t;
                bb[nt][0] = vt[bw];
                bb[nt][1] = vt[bw + 4];
            }
            #pragma unroll
            for (int mt = 0; mt < 2; ++mt) {
                u32 a[4];
                const int aw = attb + (mt * 16 + g) * 17 + ks2 * 8 + t;
                a[0] = stg[aw];
                a[1] = stg[aw + 8 * 17];
                a[2] = stg[aw + 4];
                a[3] = stg[aw + 8 * 17 + 4];
                #pragma unroll
                for (int nt = 0; nt < 4; ++nt)
                    mma_h(av[mt][nt], a, bb[nt][0], bb[nt][1]);
            }
        }
        // epilogue -> AO fp16 plane (X region): u16 scatter by channel parity
        #pragma unroll
        for (int mt = 0; mt < 2; ++mt) {
            const int chA = h * 32 + mt * 16 + g;
            const int chB = chA + 8;
            #pragma unroll
            for (int nt = 0; nt < 4; ++nt) {
                const int px0 = sub * 32 + nt * 8 + 2 * t;
                *(u16*)((char*)X + ((chA >> 1) * 72 + px0) * 4 + (chA & 1) * 2)     = f16b(av[mt][nt][0]);
                *(u16*)((char*)X + ((chA >> 1) * 72 + px0 + 1) * 4 + (chA & 1) * 2) = f16b(av[mt][nt][1]);
                *(u16*)((char*)X + ((chB >> 1) * 72 + px0) * 4 + (chB & 1) * 2)     = f16b(av[mt][nt][2]);
                *(u16*)((char*)X + ((chB >> 1) * 72 + px0 + 1) * 4 + (chB & 1) * 2) = f16b(av[mt][nt][3]);
            }
        }
    }
    __syncthreads();

    // ===== proj GEMM: 32x32 warp tiles (12 tiles = 12 warps), direct store =====
    {
        const int m_idx = wid >> 1;           // 0..5
        const int n_half = wid & 1;           // 0/1

        float acc[2][4][4];
        #pragma unroll
        for (int mt = 0; mt < 2; ++mt)
            #pragma unroll
            for (int nt = 0; nt < 4; ++nt)
                #pragma unroll
                for (int i = 0; i < 4; ++i) acc[mt][nt][i] = 0.f;

        #pragma unroll 1
        for (int ks = 0; ks < 12; ++ks) {
            uint4 Ah0 = g_wfrag[((36 + m_idx * 2 + 0) * 12 + ks) * 32 + lane];
            uint4 Ah1 = g_wfrag[((36 + m_idx * 2 + 1) * 12 + ks) * 32 + lane];
            const int base = (8 * ks + t) * 72 + g + n_half * 32;
            #pragma unroll
            for (int nt = 0; nt < 4; ++nt) {
                const u32 b0 = X[base + 8 * nt];
                const u32 b1 = X[base + 8 * nt + 288];
                mma_h(acc[0][nt], (const u32*)&Ah0, b0, b1);
                mma_h(acc[1][nt], (const u32*)&Ah1, b0, b1);
            }
        }
        const int gwp = (w0 + 2 * t) & 255;
        #pragma unroll
        for (int mt = 0; mt < 2; ++mt) {
            const int oc0 = (m_idx * 2 + mt) * 16 + g;
            #pragma unroll
            for (int nt = 0; nt < 4; ++nt) {
                const int r = n_half * 4 + nt;
                const int gh = (h0 + r) & 255;
                float* p0 = out + (((size_t)(b * CDIM + oc0)) << 16) + gh * 256 + gwp;
                *(float2*)p0 = make_float2(acc[mt][nt][0], acc[mt][nt][1]);
                float* p1 = p0 + (size_t)8 * 65536;
                *(float2*)p1 = make_float2(acc[mt][nt][2], acc[mt][nt][3]);
            }
        }
    }
}

extern "C" void kernel_launch(void* const* d_in, const int* in_sizes, int n_in,
                              void* d_out, int out_size)
{
    const float* x           = (const float*)d_in[0];
    const float* qkv_w       = (const float*)d_in[1];
    const float* dw_w        = (const float*)d_in[2];
    const float* proj_w      = (const float*)d_in[3];
    const float* temperature = (const float*)d_in[4];
    float* out               = (float*)d_out;

    prep_wfrag<<<(48 * 12 * 32 + 255) / 256, 256>>>(qkv_w, proj_w);

    cudaFuncSetAttribute(win_attn_mma, cudaFuncAttributeMaxDynamicSharedMemorySize, SMEM_DYN);
    win_attn_mma<<<NWIN, 384, SMEM_DYN>>>(x, dw_w, temperature, out);
}